// round 16
// baseline (speedup 1.0000x reference)
#include <cuda_runtime.h>
#include <math.h>

#define D_MODEL 1024
#define N_HEADS 8
#define HEAD_DIM 128
#define T_TOK 8193            // 1 class token + 8192 x rows
#define SS 8256               // padded score stride (>= 129*64)
#define S_NBLK 129
#define GRID 129              // <= 148 SMs -> all CTAs co-resident
#define ATTN_SCALE 0.08838834764831845f   // 1/sqrt(128)

// ---------------- scratch (__device__ globals) ------------------------------
__device__ float g_q0[D_MODEL];
__device__ float g_u[N_HEADS * D_MODEL];
__device__ float g_c[N_HEADS];
__device__ float g_scores[N_HEADS * SS];   // e^s per head/token (0 for pad)
__device__ float g_pZ[S_NBLK * N_HEADS];
__device__ float g_wpart[S_NBLK * N_HEADS * D_MODEL];
__device__ float g_w[N_HEADS * D_MODEL];
__device__ float g_attn0[D_MODEL];
__device__ float g_out0[D_MODEL];
__device__ unsigned g_cnt = 0;             // barrier arrive count (self-resetting)
__device__ unsigned g_gen = 0;             // barrier generation (monotonic)

// ---------------- grid barrier (all GRID blocks co-resident) -----------------
__device__ __forceinline__ void grid_barrier() {
    __threadfence();                       // make this thread's writes visible
    __syncthreads();
    if (threadIdx.x == 0) {
        unsigned gen = *(volatile unsigned*)&g_gen;   // read BEFORE arriving
        unsigned old = atomicAdd(&g_cnt, 1u);
        if (old == GRID - 1u) {
            g_cnt = 0;
            __threadfence();
            atomicAdd(&g_gen, 1u);         // release
        } else {
            while (*(volatile unsigned*)&g_gen == gen) {}
        }
    }
    __syncthreads();
    __threadfence();                       // no stale L1 after release
}

__device__ __forceinline__ float warp_sum(float v) {
#pragma unroll
    for (int o = 16; o; o >>= 1) v += __shfl_xor_sync(0xffffffffu, v, o);
    return v;
}

// ---------------- shared memory (stage union) --------------------------------
union SMem {
    struct { float4 su4[N_HEADS * 256]; float sc[N_HEADS]; float ss[N_HEADS][64]; } s3;
    struct { float sq[HEAD_DIM]; float spart[4][64]; } s2;
    struct { float sZi[N_HEADS]; float4 sred[8][32]; } s4;
    struct { float slog[2]; } s7;
};

// ---------------- the whole pipeline, one launch -----------------------------
__global__ __launch_bounds__(256)
void mega_kernel(const float* __restrict__ x,   const float* __restrict__ cls,
                 const float* __restrict__ Wq,  const float* __restrict__ bq,
                 const float* __restrict__ Wk,  const float* __restrict__ bk,
                 const float* __restrict__ Wv,  const float* __restrict__ bv,
                 const float* __restrict__ Wo,  const float* __restrict__ bo,
                 const float* __restrict__ Wc,  const float* __restrict__ bc,
                 float* __restrict__ out, int out_size) {
    __shared__ SMem sm;
    int tid = threadIdx.x;
    int w = tid >> 5, lane = tid & 31;
    int blk = blockIdx.x;

    // ===== stage 1: q0 = Wq @ cls + bq  (warp-per-row over 1024 rows) =======
    {
        int row = blk * 8 + w;
        if (row < D_MODEL) {
            const float4* wr = (const float4*)(Wq + (size_t)row * D_MODEL);
            const float4* vv = (const float4*)cls;
            float acc = 0.f;
#pragma unroll
            for (int i = 0; i < D_MODEL / 128; i++) {
                float4 a = wr[i * 32 + lane];
                float4 c = vv[i * 32 + lane];
                acc += a.x * c.x + a.y * c.y + a.z * c.z + a.w * c.w;
            }
            acc = warp_sum(acc);
            if (lane == 0) g_q0[row] = acc + bq[row];
        }
    }
    grid_barrier();

    // ===== stage 2: u[h,d] = scale * Wk_h^T q0_h ; c[h] = scale * q0_h.bk_h ==
    if (blk < 128) {
        int idx0 = blk * 64;               // 64 consecutive u-outputs, one head
        int h = idx0 >> 10;
        if (tid < HEAD_DIM) sm.s2.sq[tid] = g_q0[h * HEAD_DIM + tid];
        __syncthreads();
        int part = tid >> 6;               // 4 parts of 32 r each
        int dd = tid & 63;
        int d = (idx0 & 1023) + dd;
        const float* wp = Wk + ((size_t)h * HEAD_DIM + part * 32) * D_MODEL + d;
        float acc = 0.f;
#pragma unroll
        for (int rr = 0; rr < 32; rr++)
            acc += wp[(size_t)rr * D_MODEL] * sm.s2.sq[part * 32 + rr];
        sm.s2.spart[part][dd] = acc;
        __syncthreads();
        if (tid < 64) {
            float s = sm.s2.spart[0][tid] + sm.s2.spart[1][tid]
                    + sm.s2.spart[2][tid] + sm.s2.spart[3][tid];
            g_u[idx0 + tid] = s * ATTN_SCALE;
        }
    } else {                               // blk == 128: c[h]
        if (w < N_HEADS) {
            float acc = 0.f;
#pragma unroll
            for (int i = 0; i < HEAD_DIM / 32; i++) {
                int r = w * HEAD_DIM + i * 32 + lane;
                acc += g_q0[r] * bk[r];
            }
            acc = warp_sum(acc);
            if (lane == 0) g_c[w] = acc * ATTN_SCALE;
        }
    }
    grid_barrier();

    // ===== stage 3: fused scores -> e^s, z partials, weighted token sums =====
    {
        const float4* gu4 = (const float4*)g_u;
#pragma unroll
        for (int k = 0; k < 8; k++) sm.s3.su4[k * 256 + tid] = gu4[k * 256 + tid];
        if (tid < N_HEADS) sm.s3.sc[tid] = g_c[tid];
        __syncthreads();

        int t0 = blk * 64 + w * 8;
        const float4* rp[8];
        bool val[8];
#pragma unroll
        for (int j = 0; j < 8; j++) {
            int t = t0 + j;
            val[j] = (t < T_TOK);
            const float* p = (t == 0) ? cls : (val[j] ? x + (size_t)(t - 1) * D_MODEL : cls);
            rp[j] = (const float4*)p;
        }

        float acc[8][8];
#pragma unroll
        for (int j = 0; j < 8; j++)
#pragma unroll
            for (int h = 0; h < 8; h++) acc[j][h] = 0.f;

#pragma unroll
        for (int i = 0; i < 8; i++) {
            int f = i * 32 + lane;
            float4 u4[8];
#pragma unroll
            for (int h = 0; h < 8; h++) u4[h] = sm.s3.su4[h * 256 + f];
#pragma unroll
            for (int j = 0; j < 8; j++) {
                float4 tv = rp[j][f];
#pragma unroll
                for (int h = 0; h < 8; h++) {
                    acc[j][h] += tv.x * u4[h].x;
                    acc[j][h] += tv.y * u4[h].y;
                    acc[j][h] += tv.z * u4[h].z;
                    acc[j][h] += tv.w * u4[h].w;
                }
            }
        }

#pragma unroll
        for (int j = 0; j < 8; j++)
#pragma unroll
            for (int h = 0; h < 8; h++) {
                float s = acc[j][h];
#pragma unroll
                for (int o = 16; o; o >>= 1) s += __shfl_xor_sync(0xffffffffu, s, o);
                acc[j][h] = s;
            }

        float myv[8];
#pragma unroll
        for (int j = 0; j < 8; j++) {
            float v = acc[j][0];
#pragma unroll
            for (int h = 1; h < 8; h++) if (lane == h) v = acc[j][h];
            myv[j] = v;
        }

        if (lane < N_HEADS) {
            float c = sm.s3.sc[lane];
#pragma unroll
            for (int j = 0; j < 8; j++)
                sm.s3.ss[lane][w * 8 + j] = val[j] ? __expf(myv[j] + c) : 0.f;
        }
        __syncthreads();

        if (w < N_HEADS) {
            int h = w;
            int base = blk * 64;
            float e0 = sm.s3.ss[h][lane], e1 = sm.s3.ss[h][lane + 32];
            g_scores[h * SS + base + lane] = e0;
            g_scores[h * SS + base + lane + 32] = e1;
            float z = warp_sum(e0 + e1);
            if (lane == 0) g_pZ[blk * N_HEADS + h] = z;
        }
        __syncthreads();

        float4 wacc[N_HEADS];
#pragma unroll
        for (int h = 0; h < N_HEADS; h++) wacc[h] = make_float4(0.f, 0.f, 0.f, 0.f);
        int d4 = tid * 4;
        int base = blk * 64;
        int n = min(64, T_TOK - base);

#pragma unroll 4
        for (int i = 0; i < n; i++) {
            int gt = base + i;
            const float* tp = (gt == 0) ? cls : x + (size_t)(gt - 1) * D_MODEL;
            float4 tv = *reinterpret_cast<const float4*>(tp + d4);
#pragma unroll
            for (int h = 0; h < N_HEADS; h++) {
                float p = sm.s3.ss[h][i];
                wacc[h].x += p * tv.x;
                wacc[h].y += p * tv.y;
                wacc[h].z += p * tv.z;
                wacc[h].w += p * tv.w;
            }
        }
#pragma unroll
        for (int h = 0; h < N_HEADS; h++)
            *reinterpret_cast<float4*>(
                &g_wpart[(size_t)blk * (N_HEADS * D_MODEL) + h * D_MODEL + d4]) = wacc[h];
    }
    grid_barrier();

    // ===== stage 4: Z_h, w (64 blocks), A output (32 blocks) =================
    {
        if (w < N_HEADS) {
            float z = 0.f;
            for (int b = lane; b < S_NBLK; b += 32) z += g_pZ[b * N_HEADS + w];
            z = warp_sum(z);
            if (lane == 0) sm.s4.sZi[w] = 1.0f / z;
        }
        __syncthreads();

        if (blk < 64) {
            int col4 = blk * 32 + lane;
            const float4* wp4 = (const float4*)g_wpart;
            float4 a = make_float4(0.f, 0.f, 0.f, 0.f);
            for (int b = w; b < S_NBLK; b += 8) {
                float4 v = wp4[(size_t)b * 2048 + col4];
                a.x += v.x; a.y += v.y; a.z += v.z; a.w += v.w;
            }
            sm.s4.sred[w][lane] = a;
            __syncthreads();
            if (w == 0) {
                float4 t = sm.s4.sred[0][lane];
#pragma unroll
                for (int i = 1; i < 8; i++) {
                    float4 v = sm.s4.sred[i][lane];
                    t.x += v.x; t.y += v.y; t.z += v.z; t.w += v.w;
                }
                float zi = sm.s4.sZi[blk >> 3];
                t.x *= zi; t.y *= zi; t.z *= zi; t.w *= zi;
                ((float4*)g_w)[col4] = t;
            }
        } else if (blk < 96) {
            int s = (blk - 64) * 256 + tid;
            int t = s + 1;
            float a = 0.f;
#pragma unroll
            for (int h = 0; h < N_HEADS; h++)
                a += g_scores[h * SS + t] * sm.s4.sZi[h];
            a *= 0.125f;
            int oi = 7 + s;
            if (oi < out_size) out[oi] = a;
        }
    }
    grid_barrier();

    // ===== stage 5: attn0 = Wv @ w + bv  (warp-per-row) ======================
    if (blk < 128) {
        int row = blk * 8 + w;
        const float4* wr = (const float4*)(Wv + (size_t)row * D_MODEL);
        const float4* wv = (const float4*)(g_w + (size_t)(row >> 7) * D_MODEL);
        float acc = 0.f;
#pragma unroll
        for (int i = 0; i < D_MODEL / 128; i++) {
            float4 a = wr[i * 32 + lane];
            float4 c = wv[i * 32 + lane];
            acc += a.x * c.x + a.y * c.y + a.z * c.z + a.w * c.w;
        }
        acc = warp_sum(acc);
        if (lane == 0) g_attn0[row] = acc + bv[row];
    }
    grid_barrier();

    // ===== stage 6: out0 = Wo @ attn0 + bo ===================================
    if (blk < 128) {
        int row = blk * 8 + w;
        const float4* wr = (const float4*)(Wo + (size_t)row * D_MODEL);
        const float4* vv = (const float4*)g_attn0;
        float acc = 0.f;
#pragma unroll
        for (int i = 0; i < D_MODEL / 128; i++) {
            float4 a = wr[i * 32 + lane];
            float4 c = vv[i * 32 + lane];
            acc += a.x * c.x + a.y * c.y + a.z * c.z + a.w * c.w;
        }
        acc = warp_sum(acc);
        if (lane == 0) g_out0[row] = acc + bo[row];
    }
    grid_barrier();

    // ===== stage 7: logits, softmax, argmax (block 0) ========================
    if (blk == 0) {
        if (w < 2) {
            const float4* wr = (const float4*)(Wc + (size_t)w * D_MODEL);
            const float4* vv = (const float4*)g_out0;
            float acc = 0.f;
#pragma unroll
            for (int i = 0; i < D_MODEL / 128; i++) {
                float4 a = wr[i * 32 + lane];
                float4 c = vv[i * 32 + lane];
                acc += a.x * c.x + a.y * c.y + a.z * c.z + a.w * c.w;
            }
            acc = warp_sum(acc);
            if (lane == 0) sm.s7.slog[w] = acc + bc[w];
        }
        __syncthreads();
        if (tid == 0 && out_size >= 7) {
            float l0 = sm.s7.slog[0], l1 = sm.s7.slog[1];
            float mx = fmaxf(l0, l1);
            float e0 = __expf(l0 - mx), e1 = __expf(l1 - mx);
            float z = e0 + e1;
            float p0 = e0 / z, p1 = e1 / z;
            float am = (p1 > p0) ? 1.0f : 0.0f;
            out[0] = l0; out[1] = l1;
            out[2] = p0; out[3] = p1;
            out[4] = am;
            out[5] = p0; out[6] = p1;
        }
    }
}

// ---------------- launch -----------------------------------------------------
extern "C" void kernel_launch(void* const* d_in, const int* in_sizes, int n_in,
                              void* d_out, int out_size) {
    const float* x   = (const float*)d_in[0];
    const float* cls = (const float*)d_in[1];
    const float* Wq  = (const float*)d_in[2];
    const float* bq  = (const float*)d_in[3];
    const float* Wk  = (const float*)d_in[4];
    const float* bk  = (const float*)d_in[5];
    const float* Wv  = (const float*)d_in[6];
    const float* bv  = (const float*)d_in[7];
    const float* Wo  = (const float*)d_in[8];
    const float* bo  = (const float*)d_in[9];
    const float* Wc  = (const float*)d_in[10];
    const float* bc  = (const float*)d_in[11];
    float* out = (float*)d_out;

    mega_kernel<<<GRID, 256>>>(x, cls, Wq, bq, Wk, bk, Wv, bv, Wo, bo, Wc, bc,
                               out, out_size);
}